// round 2
// baseline (speedup 1.0000x reference)
#include <cuda_runtime.h>

// Table entry m encodes f(m-1):  f(k) = relu(1 - relu(xb - x) * rcp)
//   m in [1, n_full-1]: xb = x_full[m], rcp = 1/(x_full[m]-x_full[m-1] + 1e-9)
//   m == 0      : sentinel f(-1) = 1        -> (xb=-1e30, rcp=0)
//   m == n_full : sentinel f(n_full-1) = 0  -> (xb=+1e30, rcp=1)
__device__ float2 g_tab[8192];

__global__ void zero_kernel(float* __restrict__ out, int n4, int rem) {
    int i = blockIdx.x * blockDim.x + threadIdx.x;
    if (i < n4) {
        reinterpret_cast<float4*>(out)[i] = make_float4(0.f, 0.f, 0.f, 0.f);
    }
    if (i == 0) {
        // scalar tail (out_size not divisible by 4)
        for (int r = 0; r < rem; ++r) out[4 * n4 + r] = 0.f;
    }
}

__global__ void prep_kernel(const float* __restrict__ xf, int n_full) {
    int m = blockIdx.x * blockDim.x + threadIdx.x;
    if (m > n_full) return;
    float2 g;
    if (m == 0) {
        g = make_float2(-1e30f, 0.f);
    } else if (m == n_full) {
        g = make_float2(1e30f, 1.f);
    } else {
        float xb = xf[m];
        float xa = xf[m - 1];
        g = make_float2(xb, 1.0f / (xb - xa + 1e-9f));
    }
    g_tab[m] = g;
}

__device__ __forceinline__ float evalf(float2 g, float x) {
    // relu(1 - relu(xb - x) * rcp)
    float t = fmaxf(0.f, g.x - x);
    return fmaxf(0.f, 1.f - t * g.y);
}

__global__ void scatter_kernel(const float* __restrict__ x_eval,
                               const float* __restrict__ x_full,
                               float* __restrict__ out,
                               int n_points, int n_full) {
    int i = blockIdx.x * blockDim.x + threadIdx.x;
    if (i >= n_points) return;
    float x = x_eval[i];

    // upper_bound: lo = count of knots <= x
    int lo = 0, hi = n_full;
    while (lo < hi) {
        int mid = (lo + hi) >> 1;
        if (__ldg(x_full + mid) <= x) lo = mid + 1;
        else hi = mid;
    }
    // interval index k in [0, n_full-2]
    int k = lo - 1;
    k = (k < 0) ? 0 : k;
    int kmax = n_full - 2;
    k = (k > kmax) ? kmax : k;

    int n_cols = n_full;              // output columns == number of nodes
    int j0 = (k - 2 < 0) ? 0 : (k - 2);
    int j1 = (k + 5 > n_cols - 1) ? (n_cols - 1) : (k + 5);

    int base = i * n_cols;            // < 2^31 for this problem size
    float fprev = evalf(g_tab[j0], x);      // f(j0 - 1)
    #pragma unroll 1
    for (int j = j0; j <= j1; ++j) {
        float fj = evalf(g_tab[j + 1], x);  // f(j)
        out[base + j] = fprev - fj;
        fprev = fj;
    }
}

extern "C" void kernel_launch(void* const* d_in, const int* in_sizes, int n_in,
                              void* d_out, int out_size) {
    const float* x_eval = (const float*)d_in[0];  // (n_points, 1) float32
    const float* x_full = (const float*)d_in[1];  // (n_full,)    float32, sorted
    float* out = (float*)d_out;                   // (n_points, n_full) float32

    int n_points = in_sizes[0];
    int n_full   = in_sizes[1];

    // 1) zero-fill output (dominant cost; HBM write roofline)
    int n4  = out_size >> 2;
    int rem = out_size & 3;
    int zb  = (n4 + 255) / 256;
    if (zb < 1) zb = 1;
    zero_kernel<<<zb, 256>>>(out, n4, rem);

    // 2) build (xb, rcp) table with sentinels
    prep_kernel<<<(n_full + 1 + 255) / 256, 256>>>(x_full, n_full);

    // 3) scatter the <=8 possibly-nonzero columns per point (exact formula)
    scatter_kernel<<<(n_points + 255) / 256, 256>>>(x_eval, x_full, out,
                                                    n_points, n_full);
}